// round 3
// baseline (speedup 1.0000x reference)
#include <cuda_runtime.h>

// OSTL one-step forward, single fused kernel:
//   I      = x @ W                      (column sums over rows of W)
//   u_new  = sig_tau*u + I
//   s      = (u_new - 1 > 0) ? 1 : 0
//   u_out  = u_new - s                  (V_TH - V_RESET = 1.0)
//   J_new  = sig_tau*J + x[:,None]
//
// Outputs concatenated in d_out: [u_out (8192) | J_new (8192*8192) | s (8192)]
//
// Matvec reduction: each (col-group, row-block) block writes a partial; the
// last row-block to arrive (per column group, tracked by an atomic counter)
// sums the 128 partials in a FIXED order -> deterministic. Counter is reset
// by the finalizing block, so the kernel is graph-replay idempotent.

static constexpr int   IN_SZ  = 8192;
static constexpr int   OUT_SZ = 8192;
static constexpr float SIG_TAU = 0.8807970779778823f;  // sigmoid(2.0)

static constexpr int ROWS_PER_BLK = 64;
static constexpr int ROW_BLKS     = IN_SZ / ROWS_PER_BLK;   // 128
static constexpr int COL_BLKS     = OUT_SZ / (256 * 4);     // 8 (256 thr * float4)

// Deterministic matvec partials: one slot per (row-block, column). 4 MiB.
__device__ float g_partial[ROW_BLKS * OUT_SZ];
__device__ int   g_count[COL_BLKS];   // zero-init; reset to 0 by finalizer

__global__ void __launch_bounds__(256, 4)
fused_ostl(const float* __restrict__ x,
           const float* __restrict__ u,
           const float* __restrict__ J,
           const float* __restrict__ W,
           float*       __restrict__ Jout,
           float*       __restrict__ u_out,
           float*       __restrict__ s_out)
{
    __shared__ float xs[ROWS_PER_BLK];
    __shared__ int   is_last;
    const int t    = threadIdx.x;
    const int row0 = blockIdx.y * ROWS_PER_BLK;
    if (t < ROWS_PER_BLK) xs[t] = x[row0 + t];
    __syncthreads();

    const int col4 = blockIdx.x * 256 + t;            // float4 column index
    const float4* __restrict__ J4 = (const float4*)J;
    const float4* __restrict__ W4 = (const float4*)W;
    float4*       __restrict__ O4 = (float4*)Jout;

    float a0 = 0.f, a1 = 0.f, a2 = 0.f, a3 = 0.f;

    #pragma unroll 8
    for (int r = 0; r < ROWS_PER_BLK; ++r) {
        const size_t idx = (size_t)(row0 + r) * (OUT_SZ / 4) + col4;
        const float xi = xs[r];
        const float4 w = __ldcs(&W4[idx]);   // streaming: don't pollute L2
        const float4 j = __ldcs(&J4[idx]);
        float4 jn;
        jn.x = fmaf(SIG_TAU, j.x, xi);
        jn.y = fmaf(SIG_TAU, j.y, xi);
        jn.z = fmaf(SIG_TAU, j.z, xi);
        jn.w = fmaf(SIG_TAU, j.w, xi);
        __stcs(&O4[idx], jn);
        a0 = fmaf(xi, w.x, a0);
        a1 = fmaf(xi, w.y, a1);
        a2 = fmaf(xi, w.z, a2);
        a3 = fmaf(xi, w.w, a3);
    }

    float4* P4 = (float4*)g_partial;
    P4[(size_t)blockIdx.y * (OUT_SZ / 4) + col4] = make_float4(a0, a1, a2, a3);

    // Make partial visible, then count arrivals for this column group.
    __threadfence();
    if (t == 0) {
        int old = atomicAdd(&g_count[blockIdx.x], 1);
        is_last = (old == ROW_BLKS - 1);
    }
    __syncthreads();

    if (is_last) {
        // Fixed-order sum over the 128 partials (L2-hot) -> deterministic.
        float4 tot = make_float4(0.f, 0.f, 0.f, 0.f);
        #pragma unroll 16
        for (int k = 0; k < ROW_BLKS; ++k) {
            const float4 p = P4[(size_t)k * (OUT_SZ / 4) + col4];
            tot.x += p.x; tot.y += p.y; tot.z += p.z; tot.w += p.w;
        }
        const float4 uv = ((const float4*)u)[col4];
        tot.x = fmaf(SIG_TAU, uv.x, tot.x);
        tot.y = fmaf(SIG_TAU, uv.y, tot.y);
        tot.z = fmaf(SIG_TAU, uv.z, tot.z);
        tot.w = fmaf(SIG_TAU, uv.w, tot.w);

        float4 sp;
        sp.x = (tot.x - 1.0f) > 0.0f ? 1.0f : 0.0f;
        sp.y = (tot.y - 1.0f) > 0.0f ? 1.0f : 0.0f;
        sp.z = (tot.z - 1.0f) > 0.0f ? 1.0f : 0.0f;
        sp.w = (tot.w - 1.0f) > 0.0f ? 1.0f : 0.0f;

        float4 uo;
        uo.x = tot.x - sp.x;  // (V_TH - V_RESET) = 1.0
        uo.y = tot.y - sp.y;
        uo.z = tot.z - sp.z;
        uo.w = tot.w - sp.w;

        ((float4*)s_out)[col4] = sp;
        ((float4*)u_out)[col4] = uo;

        if (t == 0) g_count[blockIdx.x] = 0;   // replay-idempotent
    }
}

extern "C" void kernel_launch(void* const* d_in, const int* in_sizes, int n_in,
                              void* d_out, int out_size)
{
    const float* x = (const float*)d_in[0];
    const float* u = (const float*)d_in[1];
    const float* J = (const float*)d_in[2];
    const float* W = (const float*)d_in[3];

    float* out   = (float*)d_out;
    float* u_out = out;
    float* Jout  = out + OUT_SZ;
    float* s_out = out + OUT_SZ + (size_t)IN_SZ * OUT_SZ;

    fused_ostl<<<dim3(COL_BLKS, ROW_BLKS), 256>>>(x, u, J, W, Jout, u_out, s_out);
}

// round 4
// speedup vs baseline: 1.1157x; 1.1157x over previous
#include <cuda_runtime.h>

// OSTL one-step forward:
//   I      = x @ W                      (column sums over rows of W)
//   u_new  = sig_tau*u + I
//   s      = (u_new - 1 > 0) ? 1 : 0
//   u_out  = u_new - s                  (V_TH - V_RESET = 1.0)
//   J_new  = sig_tau*J + x[:,None]
//
// Outputs concatenated in d_out: [u_out (8192) | J_new (8192*8192) | s (8192)]

static constexpr int   IN_SZ  = 8192;
static constexpr int   OUT_SZ = 8192;
static constexpr float SIG_TAU = 0.8807970779778823f;  // sigmoid(2.0)

static constexpr int ROWS_PER_BLK = 64;
static constexpr int ROW_BLKS     = IN_SZ / ROWS_PER_BLK;   // 128
static constexpr int COL_BLKS     = OUT_SZ / (256 * 4);     // 8 (256 thr * float4)

// Deterministic matvec partials: one slot per (row-block, column). 4 MiB.
__device__ float g_partial[ROW_BLKS * OUT_SZ];

__global__ void __launch_bounds__(256, 4)
fused_trace_matvec(const float* __restrict__ x,
                   const float* __restrict__ J,
                   const float* __restrict__ W,
                   float*       __restrict__ Jout)
{
    __shared__ float xs[ROWS_PER_BLK];
    const int t    = threadIdx.x;
    const int row0 = blockIdx.y * ROWS_PER_BLK;
    if (t < ROWS_PER_BLK) xs[t] = x[row0 + t];
    __syncthreads();

    const int col4 = blockIdx.x * 256 + t;            // float4 column index (0..2047)
    const float4* __restrict__ J4 = (const float4*)J;
    const float4* __restrict__ W4 = (const float4*)W;
    float4*       __restrict__ O4 = (float4*)Jout;

    float a0 = 0.f, a1 = 0.f, a2 = 0.f, a3 = 0.f;

    #pragma unroll 8
    for (int r = 0; r < ROWS_PER_BLK; ++r) {
        const size_t idx = (size_t)(row0 + r) * (OUT_SZ / 4) + col4;
        const float xi = xs[r];
        const float4 w = W4[idx];
        const float4 j = J4[idx];
        float4 jn;
        jn.x = fmaf(SIG_TAU, j.x, xi);
        jn.y = fmaf(SIG_TAU, j.y, xi);
        jn.z = fmaf(SIG_TAU, j.z, xi);
        jn.w = fmaf(SIG_TAU, j.w, xi);
        O4[idx] = jn;
        a0 = fmaf(xi, w.x, a0);
        a1 = fmaf(xi, w.y, a1);
        a2 = fmaf(xi, w.z, a2);
        a3 = fmaf(xi, w.w, a3);
    }

    float4* P4 = (float4*)(g_partial + (size_t)blockIdx.y * OUT_SZ);
    P4[col4] = make_float4(a0, a1, a2, a3);
}

// Finalize v2: float4 everywhere. 128 blocks x 256 threads; each block owns
// 16 float4 columns (64 floats). 16 k-groups of 8 row-block partials each,
// reduced in fixed ascending order (k = 0..127) -> deterministic.
static constexpr int FB_COLS4 = 16;                     // float4 cols per block
static constexpr int FB_KG    = 16;                     // k-groups per block
static constexpr int K_PER    = ROW_BLKS / FB_KG;       // 8

__global__ void __launch_bounds__(256)
finalize(const float* __restrict__ u,
         float* __restrict__ u_out,
         float* __restrict__ s_out)
{
    __shared__ float4 sdata[FB_KG][FB_COLS4];

    const int c4   = threadIdx.x & (FB_COLS4 - 1);     // 0..15
    const int kg   = threadIdx.x >> 4;                 // 0..15
    const int col4 = blockIdx.x * FB_COLS4 + c4;

    const float4* P4 = (const float4*)g_partial;

    float4 sum = make_float4(0.f, 0.f, 0.f, 0.f);
    #pragma unroll
    for (int i = 0; i < K_PER; ++i) {
        const int k = kg * K_PER + i;
        const float4 p = P4[(size_t)k * (OUT_SZ / 4) + col4];
        sum.x += p.x; sum.y += p.y; sum.z += p.z; sum.w += p.w;
    }
    sdata[kg][c4] = sum;
    __syncthreads();

    if (kg == 0) {
        float4 tot = make_float4(0.f, 0.f, 0.f, 0.f);
        #pragma unroll
        for (int g = 0; g < FB_KG; ++g) {
            const float4 p = sdata[g][c4];
            tot.x += p.x; tot.y += p.y; tot.z += p.z; tot.w += p.w;
        }
        const float4 uv = ((const float4*)u)[col4];
        tot.x = fmaf(SIG_TAU, uv.x, tot.x);
        tot.y = fmaf(SIG_TAU, uv.y, tot.y);
        tot.z = fmaf(SIG_TAU, uv.z, tot.z);
        tot.w = fmaf(SIG_TAU, uv.w, tot.w);

        float4 sp;
        sp.x = (tot.x - 1.0f) > 0.0f ? 1.0f : 0.0f;
        sp.y = (tot.y - 1.0f) > 0.0f ? 1.0f : 0.0f;
        sp.z = (tot.z - 1.0f) > 0.0f ? 1.0f : 0.0f;
        sp.w = (tot.w - 1.0f) > 0.0f ? 1.0f : 0.0f;

        float4 uo;
        uo.x = tot.x - sp.x;   // (V_TH - V_RESET) = 1.0
        uo.y = tot.y - sp.y;
        uo.z = tot.z - sp.z;
        uo.w = tot.w - sp.w;

        ((float4*)s_out)[col4] = sp;
        ((float4*)u_out)[col4] = uo;
    }
}

extern "C" void kernel_launch(void* const* d_in, const int* in_sizes, int n_in,
                              void* d_out, int out_size)
{
    const float* x = (const float*)d_in[0];
    const float* u = (const float*)d_in[1];
    const float* J = (const float*)d_in[2];
    const float* W = (const float*)d_in[3];

    float* out   = (float*)d_out;
    float* u_out = out;
    float* Jout  = out + OUT_SZ;
    float* s_out = out + OUT_SZ + (size_t)IN_SZ * OUT_SZ;

    fused_trace_matvec<<<dim3(COL_BLKS, ROW_BLKS), 256>>>(x, J, W, Jout);
    finalize<<<(OUT_SZ / 4) / FB_COLS4, 256>>>(u, u_out, s_out);
}